// round 3
// baseline (speedup 1.0000x reference)
#include <cuda_runtime.h>
#include <cuda_bf16.h>
#include <cstdint>
#include <math.h>

// VectorQuantizer: N=65536 vectors, D=64, K=512 codes.
// Outputs packed into d_out (float32): [0]=loss, [1..ND]=quantized_st,
// [1+ND]=perplexity, [2+ND .. 2+ND+N)=encoding indices (as float).

#define D_DIM 64
#define K_CODES 512
#define TPB 512

typedef unsigned long long u64;

__device__ double g_sse;
__device__ int    g_hist[K_CODES];
__device__ float  g_cnorm[K_CODES];

__device__ __forceinline__ u64 ffma2(u64 a, u64 b, u64 c) {
    u64 d;
    asm("fma.rn.f32x2 %0, %1, %2, %3;" : "=l"(d) : "l"(a), "l"(b), "l"(c));
    return d;
}

__device__ __forceinline__ float2 u2f(u64 v) {
    float2 r;
    r.x = __uint_as_float((unsigned)(v & 0xFFFFFFFFull));
    r.y = __uint_as_float((unsigned)(v >> 32));
    return r;
}

// ---------------------------------------------------------------------------
// Init: zero accumulators/histogram, precompute codebook squared norms
// (fp32 products, double accumulation, rounded to fp32 like the reference).
// ---------------------------------------------------------------------------
__global__ void vq_init(const float* __restrict__ cb) {
    int t = threadIdx.x;  // 512 threads, one code each
    g_hist[t] = 0;
    const float* c = cb + t * D_DIM;
    double s = 0.0;
#pragma unroll
    for (int i = 0; i < D_DIM; i++) {
        float p = __fmul_rn(c[i], c[i]);  // fp32-rounded square
        s += (double)p;
    }
    g_cnorm[t] = (float)s;
    if (t == 0) g_sse = 0.0;
}

// ---------------------------------------------------------------------------
// Main: one thread per input vector. Codebook in shared memory.
// Packed f32x2 FMAs (FFMA2) for the distance dot-products.
// Score replicates the reference's fp32 rounding:
//   s = fl( fl( A - 2*dot ) + C ),  A = fp32(||x||^2), C = fp32(||c||^2)
// Adding to A~64 quantizes scores to a ~7.6e-6 grid; equal grid values
// tie-break to the LOWER index (strict-< ascending scan), matching argmin.
// ---------------------------------------------------------------------------
__global__ __launch_bounds__(TPB, 1)
void vq_main(const float* __restrict__ x, const float* __restrict__ cb,
             float* __restrict__ outq, float* __restrict__ outidx) {
    extern __shared__ float scb[];  // 512*64 floats = 128 KB

    // Cooperative codebook load (broadcast-friendly for later reads)
    {
        const float4* src = (const float4*)cb;
        float4* dst = (float4*)scb;
        for (int i = threadIdx.x; i < (K_CODES * D_DIM) / 4; i += TPB)
            dst[i] = src[i];
    }
    __syncthreads();

    int vid = blockIdx.x * TPB + threadIdx.x;

    // Load input vector into registers as 32 packed f32x2 words.
    u64 xs[D_DIM / 2];
    {
        const ulonglong2* xr = (const ulonglong2*)(x + (size_t)vid * D_DIM);
#pragma unroll
        for (int i = 0; i < D_DIM / 4; i++) {
            ulonglong2 v = xr[i];
            xs[2 * i]     = v.x;
            xs[2 * i + 1] = v.y;
        }
    }

    // A = fp32(||x||^2): fp32 squares, double accumulation, round to fp32.
    float A;
    {
        double sa = 0.0;
#pragma unroll
        for (int j = 0; j < D_DIM / 2; j++) {
            float2 xx = u2f(xs[j]);
            sa += (double)__fmul_rn(xx.x, xx.x);
            sa += (double)__fmul_rn(xx.y, xx.y);
        }
        A = (float)sa;
    }

    float best = 3.4e38f;
    int   bi   = 0;

    // 4 codes per group, 2 packed accumulators per code (ILP = 8 FMA chains)
    for (int k = 0; k < K_CODES; k += 4) {
        const ulonglong2* c0 = (const ulonglong2*)(scb + (k + 0) * D_DIM);
        const ulonglong2* c1 = (const ulonglong2*)(scb + (k + 1) * D_DIM);
        const ulonglong2* c2 = (const ulonglong2*)(scb + (k + 2) * D_DIM);
        const ulonglong2* c3 = (const ulonglong2*)(scb + (k + 3) * D_DIM);
        u64 a0 = 0, b0 = 0, a1 = 0, b1 = 0, a2 = 0, b2 = 0, a3 = 0, b3 = 0;
#pragma unroll
        for (int d = 0; d < D_DIM / 4; d++) {
            ulonglong2 v0 = c0[d], v1 = c1[d], v2 = c2[d], v3 = c3[d];
            u64 xa = xs[2 * d], xb = xs[2 * d + 1];
            a0 = ffma2(xa, v0.x, a0);  b0 = ffma2(xb, v0.y, b0);
            a1 = ffma2(xa, v1.x, a1);  b1 = ffma2(xb, v1.y, b1);
            a2 = ffma2(xa, v2.x, a2);  b2 = ffma2(xb, v2.y, b2);
            a3 = ffma2(xa, v3.x, a3);  b3 = ffma2(xb, v3.y, b3);
        }
        float2 fa, fb;
        fa = u2f(a0); fb = u2f(b0);
        float dot0 = (fa.x + fa.y) + (fb.x + fb.y);
        fa = u2f(a1); fb = u2f(b1);
        float dot1 = (fa.x + fa.y) + (fb.x + fb.y);
        fa = u2f(a2); fb = u2f(b2);
        float dot2 = (fa.x + fa.y) + (fb.x + fb.y);
        fa = u2f(a3); fb = u2f(b3);
        float dot3 = (fa.x + fa.y) + (fb.x + fb.y);

        // s = fl( fl(A - 2*dot) + C )   (2*dot is exact; fmaf == sub here)
        float s0 = __fadd_rn(__fmaf_rn(-2.f, dot0, A), __ldg(&g_cnorm[k + 0]));
        float s1 = __fadd_rn(__fmaf_rn(-2.f, dot1, A), __ldg(&g_cnorm[k + 1]));
        float s2 = __fadd_rn(__fmaf_rn(-2.f, dot2, A), __ldg(&g_cnorm[k + 2]));
        float s3 = __fadd_rn(__fmaf_rn(-2.f, dot3, A), __ldg(&g_cnorm[k + 3]));

        // Strict-< ascending scan preserves first-min (jnp.argmin) semantics
        if (s0 < best) { best = s0; bi = k + 0; }
        if (s1 < best) { best = s1; bi = k + 1; }
        if (s2 < best) { best = s2; bi = k + 2; }
        if (s3 < best) { best = s3; bi = k + 3; }
    }

    outidx[vid] = (float)bi;
    atomicAdd(&g_hist[bi], 1);

    // Epilogue: quantized_st = x + (q - x) (reference's exact op order),
    // and SSE accumulation of (q - x)^2.
    // NOTE: outq points at d_out + 1 (odd float offset) -> only 4-byte
    // aligned. All stores here MUST be scalar 32-bit stores.
    const float* q = scb + bi * D_DIM;
    float* o = outq + (size_t)vid * D_DIM;
    float sse = 0.f;
#pragma unroll
    for (int j = 0; j < D_DIM / 2; j++) {
        float2 xx = u2f(xs[j]);
        float q0 = q[2 * j], q1 = q[2 * j + 1];
        float d0 = __fadd_rn(q0, -xx.x), d1 = __fadd_rn(q1, -xx.y);
        sse += d0 * d0 + d1 * d1;
        o[2 * j]     = __fadd_rn(xx.x, d0);
        o[2 * j + 1] = __fadd_rn(xx.y, d1);
    }

    // Warp reduce, then one double atomic per warp
#pragma unroll
    for (int off = 16; off > 0; off >>= 1)
        sse += __shfl_xor_sync(0xFFFFFFFFu, sse, off);
    if ((threadIdx.x & 31) == 0)
        atomicAdd(&g_sse, (double)sse);
}

// ---------------------------------------------------------------------------
// Finalize: loss and perplexity.
// ---------------------------------------------------------------------------
__global__ void vq_final(float* __restrict__ out, int nd, int n) {
    int t = threadIdx.x;  // 512 threads
    float p = (float)g_hist[t] / (float)n;
    float e = p * logf(p + 1e-10f);

    __shared__ float red[16];
#pragma unroll
    for (int off = 16; off > 0; off >>= 1)
        e += __shfl_xor_sync(0xFFFFFFFFu, e, off);
    if ((t & 31) == 0) red[t >> 5] = e;
    __syncthreads();
    if (t < 16) {
        float v = red[t];
#pragma unroll
        for (int off = 8; off > 0; off >>= 1)
            v += __shfl_xor_sync(0xFFFFu, v, off);
        if (t == 0) {
            out[1 + nd] = expf(-v);                 // perplexity
            float m = (float)(g_sse / (double)nd);  // mean squared error
            out[0] = m + 0.25f * m;                 // q_loss + 0.25 * e_loss
        }
    }
}

// ---------------------------------------------------------------------------
extern "C" void kernel_launch(void* const* d_in, const int* in_sizes, int n_in,
                              void* d_out, int out_size) {
    const float* x  = (const float*)d_in[0];  // inputs  (64,32,32,64) f32
    const float* cb = (const float*)d_in[1];  // codebook (512,64)     f32
    float* out = (float*)d_out;

    int nd = in_sizes[0];     // 4194304
    int n  = nd / D_DIM;      // 65536

    cudaFuncSetAttribute(vq_main, cudaFuncAttributeMaxDynamicSharedMemorySize,
                         K_CODES * D_DIM * (int)sizeof(float));

    vq_init<<<1, K_CODES>>>(cb);
    vq_main<<<n / TPB, TPB, K_CODES * D_DIM * sizeof(float)>>>(
        x, cb, out + 1, out + 2 + nd);
    vq_final<<<1, K_CODES>>>(out, nd, n);
}

// round 4
// speedup vs baseline: 1.2102x; 1.2102x over previous
#include <cuda_runtime.h>
#include <cuda_bf16.h>
#include <cstdint>
#include <math.h>

// VectorQuantizer: N=65536 vectors, D=64, K=512 codes.
// d_out (float32): [0]=loss, [1..ND]=quantized_st, [1+ND]=perplexity,
// [2+ND..2+ND+N)=encoding indices (as float).
//
// R4: no init kernel (per-CTA partials, nothing to zero), V=2 vectors/thread
// at TPB=256 (no spills, FMA:LDS issue ratio 4:1), cnorm from smem.

#define D_DIM 64
#define K_CODES 512
#define TPB 256
#define VPT 2
#define NBLK 128  // 65536 / (TPB*VPT)

typedef unsigned long long u64;

__device__ int    g_hist_part[NBLK][K_CODES];
__device__ double g_sse_part[NBLK];

__device__ __forceinline__ u64 ffma2(u64 a, u64 b, u64 c) {
    u64 d;
    asm("fma.rn.f32x2 %0, %1, %2, %3;" : "=l"(d) : "l"(a), "l"(b), "l"(c));
    return d;
}

__device__ __forceinline__ float2 u2f(u64 v) {
    float2 r;
    r.x = __uint_as_float((unsigned)(v & 0xFFFFFFFFull));
    r.y = __uint_as_float((unsigned)(v >> 32));
    return r;
}

// Shared layout (bytes): scb 131072 | scn 2048 | shist 2048 | sred 64
#define SMEM_BYTES (K_CODES * D_DIM * 4 + K_CODES * 4 + K_CODES * 4 + 64)

__global__ __launch_bounds__(TPB, 1)
void vq_main(const float* __restrict__ x, const float* __restrict__ cb,
             float* __restrict__ outq, float* __restrict__ outidx) {
    extern __shared__ float scb[];                     // [512*64]
    float*  scn   = scb + K_CODES * D_DIM;             // [512]
    int*    shist = (int*)(scn + K_CODES);             // [512]
    double* sred  = (double*)(shist + K_CODES);        // [8]

    const int tid = threadIdx.x;

    // Cooperative codebook load + zero smem histogram
    {
        const float4* src = (const float4*)cb;
        float4* dst = (float4*)scb;
#pragma unroll
        for (int i = tid; i < (K_CODES * D_DIM) / 4; i += TPB)
            dst[i] = src[i];
        shist[tid] = 0;
        shist[tid + TPB] = 0;
    }
    __syncthreads();

    // Codebook norms: fp32 squares, double accumulation, round to fp32.
    // Thread t handles codes t and t+256 (two interleaved DADD chains).
    {
        const float4* r0 = (const float4*)(scb + tid * D_DIM);
        const float4* r1 = (const float4*)(scb + (tid + TPB) * D_DIM);
        double s0 = 0.0, s1 = 0.0;
#pragma unroll
        for (int j = 0; j < D_DIM / 4; j++) {
            float4 v0 = r0[j], v1 = r1[j];
            s0 += (double)__fmul_rn(v0.x, v0.x); s0 += (double)__fmul_rn(v0.y, v0.y);
            s0 += (double)__fmul_rn(v0.z, v0.z); s0 += (double)__fmul_rn(v0.w, v0.w);
            s1 += (double)__fmul_rn(v1.x, v1.x); s1 += (double)__fmul_rn(v1.y, v1.y);
            s1 += (double)__fmul_rn(v1.z, v1.z); s1 += (double)__fmul_rn(v1.w, v1.w);
        }
        scn[tid]       = (float)s0;
        scn[tid + TPB] = (float)s1;
    }
    __syncthreads();

    const int vid0 = blockIdx.x * (TPB * VPT) + tid;
    const int vid1 = vid0 + TPB;

    // Load both input vectors into registers (packed f32x2 words).
    u64 xs0[D_DIM / 2], xs1[D_DIM / 2];
    {
        const ulonglong2* xr0 = (const ulonglong2*)(x + (size_t)vid0 * D_DIM);
        const ulonglong2* xr1 = (const ulonglong2*)(x + (size_t)vid1 * D_DIM);
#pragma unroll
        for (int i = 0; i < D_DIM / 4; i++) {
            ulonglong2 v0 = xr0[i], v1 = xr1[i];
            xs0[2 * i] = v0.x; xs0[2 * i + 1] = v0.y;
            xs1[2 * i] = v1.x; xs1[2 * i + 1] = v1.y;
        }
    }

    // A = fp32(||x||^2) per vector (fp32 squares, double accumulation).
    float A0, A1;
    {
        double sa0 = 0.0, sa1 = 0.0;
#pragma unroll
        for (int j = 0; j < D_DIM / 2; j++) {
            float2 p0 = u2f(xs0[j]), p1 = u2f(xs1[j]);
            sa0 += (double)__fmul_rn(p0.x, p0.x); sa0 += (double)__fmul_rn(p0.y, p0.y);
            sa1 += (double)__fmul_rn(p1.x, p1.x); sa1 += (double)__fmul_rn(p1.y, p1.y);
        }
        A0 = (float)sa0; A1 = (float)sa1;
    }

    float best0 = 3.4e38f, best1 = 3.4e38f;
    int   bi0 = 0, bi1 = 0;

    // 2 codes x 2 vectors per group: 8 independent FFMA2 chains,
    // 2 LDS.128 per 8 FFMA2 (issue ratio 4:1).
    for (int k = 0; k < K_CODES; k += 2) {
        const ulonglong2* c0 = (const ulonglong2*)(scb + k * D_DIM);
        const ulonglong2* c1 = (const ulonglong2*)(scb + k * D_DIM + D_DIM);
        u64 a00 = 0, b00 = 0, a01 = 0, b01 = 0;
        u64 a10 = 0, b10 = 0, a11 = 0, b11 = 0;
#pragma unroll
        for (int d = 0; d < D_DIM / 4; d++) {
            ulonglong2 v0 = c0[d], v1 = c1[d];
            u64 xa0 = xs0[2 * d], xb0 = xs0[2 * d + 1];
            u64 xa1 = xs1[2 * d], xb1 = xs1[2 * d + 1];
            a00 = ffma2(xa0, v0.x, a00);  b00 = ffma2(xb0, v0.y, b00);
            a10 = ffma2(xa1, v0.x, a10);  b10 = ffma2(xb1, v0.y, b10);
            a01 = ffma2(xa0, v1.x, a01);  b01 = ffma2(xb0, v1.y, b01);
            a11 = ffma2(xa1, v1.x, a11);  b11 = ffma2(xb1, v1.y, b11);
        }
        float2 fa, fb;
        fa = u2f(a00); fb = u2f(b00);
        float dot00 = (fa.x + fa.y) + (fb.x + fb.y);
        fa = u2f(a01); fb = u2f(b01);
        float dot01 = (fa.x + fa.y) + (fb.x + fb.y);
        fa = u2f(a10); fb = u2f(b10);
        float dot10 = (fa.x + fa.y) + (fb.x + fb.y);
        fa = u2f(a11); fb = u2f(b11);
        float dot11 = (fa.x + fa.y) + (fb.x + fb.y);

        float C0 = scn[k], C1 = scn[k + 1];
        // s = fl( fl(A - 2*dot) + C )  -- reference's fp32 rounding structure
        float s00 = __fadd_rn(__fmaf_rn(-2.f, dot00, A0), C0);
        float s01 = __fadd_rn(__fmaf_rn(-2.f, dot01, A0), C1);
        float s10 = __fadd_rn(__fmaf_rn(-2.f, dot10, A1), C0);
        float s11 = __fadd_rn(__fmaf_rn(-2.f, dot11, A1), C1);

        // Strict-< ascending scan == jnp.argmin first-min tie-break
        if (s00 < best0) { best0 = s00; bi0 = k; }
        if (s01 < best0) { best0 = s01; bi0 = k + 1; }
        if (s10 < best1) { best1 = s10; bi1 = k; }
        if (s11 < best1) { best1 = s11; bi1 = k + 1; }
    }

    outidx[vid0] = (float)bi0;
    outidx[vid1] = (float)bi1;
    atomicAdd(&shist[bi0], 1);
    atomicAdd(&shist[bi1], 1);

    // Epilogue: quantized_st = x + (q - x); SSE of (q - x)^2.
    // outq is d_out+1 (odd float offset): scalar 32-bit stores ONLY.
    float sse = 0.f;
    {
        const float* q0 = scb + bi0 * D_DIM;
        float* o0 = outq + (size_t)vid0 * D_DIM;
#pragma unroll
        for (int j = 0; j < D_DIM / 2; j++) {
            float2 xx = u2f(xs0[j]);
            float d0 = __fadd_rn(q0[2 * j],     -xx.x);
            float d1 = __fadd_rn(q0[2 * j + 1], -xx.y);
            sse += d0 * d0 + d1 * d1;
            o0[2 * j]     = __fadd_rn(xx.x, d0);
            o0[2 * j + 1] = __fadd_rn(xx.y, d1);
        }
        const float* q1 = scb + bi1 * D_DIM;
        float* o1 = outq + (size_t)vid1 * D_DIM;
#pragma unroll
        for (int j = 0; j < D_DIM / 2; j++) {
            float2 xx = u2f(xs1[j]);
            float d0 = __fadd_rn(q1[2 * j],     -xx.x);
            float d1 = __fadd_rn(q1[2 * j + 1], -xx.y);
            sse += d0 * d0 + d1 * d1;
            o1[2 * j]     = __fadd_rn(xx.x, d0);
            o1[2 * j + 1] = __fadd_rn(xx.y, d1);
        }
    }

    // Block-reduce SSE -> per-CTA partial (write, not accumulate)
#pragma unroll
    for (int off = 16; off > 0; off >>= 1)
        sse += __shfl_xor_sync(0xFFFFFFFFu, sse, off);
    if ((tid & 31) == 0) sred[tid >> 5] = (double)sse;
    __syncthreads();
    if (tid == 0) {
        double s = 0.0;
#pragma unroll
        for (int w = 0; w < TPB / 32; w++) s += sred[w];
        g_sse_part[blockIdx.x] = s;
    }

    // Per-CTA histogram partial (write, not accumulate)
    g_hist_part[blockIdx.x][tid]       = shist[tid];
    g_hist_part[blockIdx.x][tid + TPB] = shist[tid + TPB];
}

// ---------------------------------------------------------------------------
// Finalize: sum partials -> loss and perplexity.
// ---------------------------------------------------------------------------
__global__ void vq_final(float* __restrict__ out, int nd, int n) {
    int t = threadIdx.x;  // 512 threads
    __shared__ double ssum;
    __shared__ float  red[16];

    // Warp 0: reduce SSE partials (4 per lane, then shfl)
    if (t < 32) {
        double s = g_sse_part[t] + g_sse_part[t + 32] +
                   g_sse_part[t + 64] + g_sse_part[t + 96];
#pragma unroll
        for (int off = 16; off > 0; off >>= 1)
            s += __shfl_xor_sync(0xFFFFFFFFu, s, off);
        if (t == 0) ssum = s;
    }

    // Histogram totals: code t summed over 128 CTA partials
    int h = 0;
#pragma unroll 8
    for (int b = 0; b < NBLK; b++) h += g_hist_part[b][t];

    float p = (float)h / (float)n;
    float e = p * logf(p + 1e-10f);

#pragma unroll
    for (int off = 16; off > 0; off >>= 1)
        e += __shfl_xor_sync(0xFFFFFFFFu, e, off);
    if ((t & 31) == 0) red[t >> 5] = e;
    __syncthreads();
    if (t < 16) {
        float v = red[t];
#pragma unroll
        for (int off = 8; off > 0; off >>= 1)
            v += __shfl_xor_sync(0xFFFFu, v, off);
        if (t == 0) {
            out[1 + nd] = expf(-v);                  // perplexity
            float m = (float)(ssum / (double)nd);    // mean squared error
            out[0] = m + 0.25f * m;                  // q_loss + 0.25*e_loss
        }
    }
}

// ---------------------------------------------------------------------------
extern "C" void kernel_launch(void* const* d_in, const int* in_sizes, int n_in,
                              void* d_out, int out_size) {
    const float* x  = (const float*)d_in[0];  // inputs  (64,32,32,64) f32
    const float* cb = (const float*)d_in[1];  // codebook (512,64)     f32
    float* out = (float*)d_out;

    int nd = in_sizes[0];     // 4194304
    int n  = nd / D_DIM;      // 65536

    cudaFuncSetAttribute(vq_main, cudaFuncAttributeMaxDynamicSharedMemorySize,
                         SMEM_BYTES);

    vq_main<<<NBLK, TPB, SMEM_BYTES>>>(x, cb, out + 1, out + 2 + nd);
    vq_final<<<1, K_CODES>>>(out, nd, n);
}